// round 11
// baseline (speedup 1.0000x reference)
#include <cuda_runtime.h>
#include <cuda_bf16.h>
#include <cstdint>

#define NB   8            // b's per tile (one warp per b)
#define TPB  256
#define EPS  1e-6f
typedef unsigned long long ull;

// per-stage floats: sRp | sgt | gsym
#define RP_F    (NB * 576)          // 4608
#define GT_F    (NB * 9)            // 72
#define GS_F    (NB * 12 * 12)      // 1152 (12-float padded rows per (b,s))
#define STAGE_F (RP_F + GT_F + GS_F)   // 5832 floats = 23328 B (16B mult)
#define SMEM_BYTES (2 * STAGE_F * 4)

__device__ float g_partial[1024];
__device__ unsigned int g_count = 0;    // self-resets via atomicInc wrap

__global__ __launch_bounds__(TPB, 4)
void geo_pipe(const float* __restrict__ R_pred,
              const float* __restrict__ R_gt,
              const float* __restrict__ rot,
              float* __restrict__ out,
              int B, int ntiles, int grid, float invB)
{
    extern __shared__ float sm[];
    __shared__ float ssum;
    __shared__ int slast;

    const int tid  = threadIdx.x;
    const int wid  = tid >> 5;
    const int lane = tid & 31;

    // per-thread rot constants for the Gsym phase (loaded once)
    float r0 = 0.f, r1 = 0.f, r2 = 0.f;
    int gs_off = 0, gt_off = 0;
    if (tid < 108) {
        const int s = tid / 9, e = tid - s * 9, ii = e / 3, kk = e - ii * 3;
        r0 = __ldg(rot + s * 9 + ii * 3 + 0);
        r1 = __ldg(rot + s * 9 + ii * 3 + 1);
        r2 = __ldg(rot + s * 9 + ii * 3 + 2);
        gs_off = s * 12 + e;     // within a b's 144-float gsym row block
        gt_off = kk;
    }
    if (tid == 0) ssum = 0.0f;

    // stage tile t into buffer p (cp.async; R_pred as 16B, R_gt as 4B)
    auto stage = [&](int t, int p) {
        const int b0 = t * NB;
        const int nb = min(NB, B - b0);
        float* S = sm + p * STAGE_F;
        const float4* src = reinterpret_cast<const float4*>(R_pred + (size_t)b0 * 576);
        uint32_t d0 = (uint32_t)__cvta_generic_to_shared(S);
        const int n4 = nb * 144;
        for (int i = tid; i < n4; i += TPB)
            asm volatile("cp.async.cg.shared.global [%0], [%1], 16;"
                         :: "r"(d0 + (uint32_t)i * 16u), "l"(src + i) : "memory");
        if (tid < nb * 9) {
            uint32_t d1 = (uint32_t)__cvta_generic_to_shared(S + RP_F) + (uint32_t)tid * 4u;
            asm volatile("cp.async.ca.shared.global [%0], [%1], 4;"
                         :: "r"(d1), "l"(R_gt + (size_t)b0 * 9 + tid) : "memory");
        }
    };

    int t = blockIdx.x;
    int p = 0;
    stage(t, 0);
    asm volatile("cp.async.commit_group;" ::: "memory");

    float fsum = 0.0f;   // unused per-thread; sums go to ssum via lane0

    for (; t < ntiles; t += grid, p ^= 1) {
        const int nxt = t + grid;
        if (nxt < ntiles) {
            stage(nxt, p ^ 1);
            asm volatile("cp.async.commit_group;" ::: "memory");
            asm volatile("cp.async.wait_group 1;" ::: "memory");
        } else {
            asm volatile("cp.async.wait_group 0;" ::: "memory");
        }
        __syncthreads();

        const int nb = min(NB, B - t * NB);
        float* S = sm + p * STAGE_F;

        // ---- Gsym[bl][s][e] = sum_j rot[s,i,j]*R_gt[bl,j,k] (un-duplicated) ----
        if (tid < 108) {
            float* G = S + RP_F + GT_F;
            const float* gt = S + RP_F + gt_off;
            for (int bl = 0; bl < nb; bl++) {
                float v = fmaf(r2, gt[bl * 9 + 6],
                          fmaf(r1, gt[bl * 9 + 3],
                               r0 * gt[bl * 9 + 0]));
                G[bl * 144 + gs_off] = v;
            }
        }
        __syncthreads();

        // ---- hot: one warp per b, 2 candidates per lane, element-pair f32x2 ----
        if (wid < nb) {
            // 18 floats (2 candidates) as 9 aligned ull pairs, zero movs
            ull A[9];
            const float* rpb = S + wid * 576 + lane * 18;
            #pragma unroll
            for (int k = 0; k < 9; k++)
                A[k] = *reinterpret_cast<const ull*>(rpb + 2 * k);   // LDS.64, conflict-free

            // candidate1 pairs straddle; repack 4 ulls
            float2 a4 = *reinterpret_cast<float2*>(&A[4]);
            float2 a5 = *reinterpret_cast<float2*>(&A[5]);
            float2 a6 = *reinterpret_cast<float2*>(&A[6]);
            float2 a7 = *reinterpret_cast<float2*>(&A[7]);
            float2 a8 = *reinterpret_cast<float2*>(&A[8]);
            ull P0, P1, P2, P3;
            asm("mov.b64 %0, {%1, %2};" : "=l"(P0) : "f"(a4.y), "f"(a5.x));
            asm("mov.b64 %0, {%1, %2};" : "=l"(P1) : "f"(a5.y), "f"(a6.x));
            asm("mov.b64 %0, {%1, %2};" : "=l"(P2) : "f"(a6.y), "f"(a7.x));
            asm("mov.b64 %0, {%1, %2};" : "=l"(P3) : "f"(a7.y), "f"(a8.x));
            const float c0e8 = a4.x;
            const float c1e8 = a8.y;

            const float* G = S + RP_F + GT_F + wid * 144;   // warp-uniform base
            float cmax = -1e30f;
            #pragma unroll
            for (int s = 0; s < 12; s++) {
                const float* gs = G + s * 12;
                ulonglong2 Q0 = *reinterpret_cast<const ulonglong2*>(gs);      // (g0,g1),(g2,g3)
                ulonglong2 Q1 = *reinterpret_cast<const ulonglong2*>(gs + 4);  // (g4,g5),(g6,g7)
                float g8 = gs[8];

                ull acc0, acc1;
                asm("mul.rn.f32x2 %0, %1, %2;"     : "=l"(acc0) : "l"(A[0]), "l"(Q0.x));
                asm("mul.rn.f32x2 %0, %1, %2;"     : "=l"(acc1) : "l"(P0),   "l"(Q0.x));
                asm("fma.rn.f32x2 %0, %1, %2, %3;" : "=l"(acc0) : "l"(A[1]), "l"(Q0.y), "l"(acc0));
                asm("fma.rn.f32x2 %0, %1, %2, %3;" : "=l"(acc1) : "l"(P1),   "l"(Q0.y), "l"(acc1));
                asm("fma.rn.f32x2 %0, %1, %2, %3;" : "=l"(acc0) : "l"(A[2]), "l"(Q1.x), "l"(acc0));
                asm("fma.rn.f32x2 %0, %1, %2, %3;" : "=l"(acc1) : "l"(P2),   "l"(Q1.x), "l"(acc1));
                asm("fma.rn.f32x2 %0, %1, %2, %3;" : "=l"(acc0) : "l"(A[3]), "l"(Q1.y), "l"(acc0));
                asm("fma.rn.f32x2 %0, %1, %2, %3;" : "=l"(acc1) : "l"(P3),   "l"(Q1.y), "l"(acc1));

                float2 u0 = *reinterpret_cast<float2*>(&acc0);
                float2 u1 = *reinterpret_cast<float2*>(&acc1);
                float t0 = fmaf(c0e8, g8, u0.x + u0.y);
                float t1 = fmaf(c1e8, g8, u1.x + u1.y);
                cmax = fmaxf(cmax, fmaxf(t0, t1));
            }

            // full-warp max (one b per warp)
            #pragma unroll
            for (int w = 16; w >= 1; w >>= 1)
                cmax = fmaxf(cmax, __shfl_xor_sync(0xFFFFFFFFu, cmax, w));

            if (lane == 0) {
                float cosv = (cmax - 1.0f) * 0.5f;
                cosv = fminf(fmaxf(cosv, -1.0f + EPS), 1.0f - EPS);
                atomicAdd(&ssum, acosf(cosv));
            }
        }
        __syncthreads();   // protect buffer p before next iteration stages into it
    }
    (void)fsum;

    // ---- publish per-CTA sum; last CTA reduces (counter wraps to 0) ----
    if (tid == 0) {
        g_partial[blockIdx.x] = ssum;
        __threadfence();
        unsigned int old = atomicInc(&g_count, (unsigned int)(grid - 1));
        slast = (old == (unsigned int)(grid - 1));
    }
    __syncthreads();

    if (slast) {
        __shared__ float warpsum[TPB / 32];
        float v = 0.0f;
        for (int i = tid; i < grid; i += TPB) v += __ldcg(&g_partial[i]);
        #pragma unroll
        for (int w = 16; w >= 1; w >>= 1)
            v += __shfl_xor_sync(0xFFFFFFFFu, v, w);
        if ((tid & 31) == 0) warpsum[tid >> 5] = v;
        __syncthreads();
        if (tid < TPB / 32) {
            float w2 = warpsum[tid];
            #pragma unroll
            for (int w = TPB / 64; w >= 1; w >>= 1)
                w2 += __shfl_xor_sync(0xFFu, w2, w);
            if (tid == 0) out[0] = w2 * invB;
        }
    }
}

extern "C" void kernel_launch(void* const* d_in, const int* in_sizes, int n_in,
                              void* d_out, int out_size)
{
    const float* R_pred = (const float*)d_in[0];
    const float* R_gt   = (const float*)d_in[1];
    const float* rot    = (const float*)d_in[2];
    float* out = (float*)d_out;

    const int B = in_sizes[1] / 9;
    const int ntiles = (B + NB - 1) / NB;
    const int grid = (ntiles < 592) ? ntiles : 592;   // 4 CTAs/SM x 148 SMs

    cudaFuncSetAttribute(geo_pipe, cudaFuncAttributeMaxDynamicSharedMemorySize, SMEM_BYTES);
    geo_pipe<<<grid, TPB, SMEM_BYTES>>>(R_pred, R_gt, rot, out,
                                        B, ntiles, grid, 1.0f / (float)B);
}

// round 12
// speedup vs baseline: 1.2570x; 1.2570x over previous
#include <cuda_runtime.h>
#include <cuda_bf16.h>
#include <cstdint>

#define NB   8            // b's per tile
#define TPB  128          // 16 threads per b, 4 candidates per thread
#define EPS  1e-6f
typedef unsigned long long ull;

#define RP_F     (NB * 576)        // 4608 floats per stage (18432 B)
#define STAGE_F  RP_F
#define SMEM_BYTES (2 * STAGE_F * 4)   // 36864 B dynamic

__device__ float g_partial[1024];
__device__ unsigned int g_count = 0;    // self-resets via atomicInc wrap

__global__ __launch_bounds__(TPB, 6)
void geo_pipe(const float* __restrict__ R_pred,
              const float* __restrict__ R_gt,
              const float* __restrict__ rot,
              float* __restrict__ out,
              int B, int ntiles, int grid, float invB)
{
    extern __shared__ float sm[];          // 2 x RP_F staging buffers
    __shared__ float gdup[240];            // rot duplicated pairs (80B per s), warp-uniform
    __shared__ float ssum;
    __shared__ int slast;

    const int tid = threadIdx.x;
    const int bl  = tid >> 4;              // local b within tile
    const int m   = tid & 15;              // candidate group (4 candidates)

    if (tid < 108) {
        const int s = tid / 9, e = tid - s * 9;
        float v = __ldg(rot + tid);
        gdup[s * 20 + e * 2]     = v;
        gdup[s * 20 + e * 2 + 1] = v;
    }
    if (tid == 0) ssum = 0.0f;

    // stage tile t's R_pred slice into buffer p (coalesced 16B cp.async)
    auto stage = [&](int t, int p) {
        const int nb = min(NB, B - t * NB);
        const int n4 = nb * 144;
        const float4* src = reinterpret_cast<const float4*>(R_pred + (size_t)t * NB * 576);
        uint32_t d0 = (uint32_t)__cvta_generic_to_shared(sm + p * STAGE_F) + (uint32_t)tid * 16u;
        #pragma unroll
        for (int j = 0; j < 9; j++) {
            if (tid + j * TPB < n4)
                asm volatile("cp.async.cg.shared.global [%0], [%1], 16;"
                             :: "r"(d0 + j * (TPB * 16u)), "l"(src + tid + j * TPB) : "memory");
        }
        asm volatile("cp.async.commit_group;" ::: "memory");
    };

    int t = blockIdx.x;
    stage(t, 0);
    int p = 0;

    for (; t < ntiles; t += grid, p ^= 1) {
        const int nxt = t + grid;
        if (nxt < ntiles) {
            stage(nxt, p ^ 1);                                  // keep DRAM busy
            asm volatile("cp.async.wait_group 1;" ::: "memory");  // current tile ready
        } else {
            asm volatile("cp.async.wait_group 0;" ::: "memory");
        }
        __syncthreads();

        const int nb = min(NB, B - t * NB);
        const float* S = sm + p * STAGE_F;
        float cmax = -1e30f;

        if (bl < nb) {
            const int b = t * NB + bl;

            // R_gt[b]: 9 x LDG.32, L2-resident, half-warp-uniform addresses
            float g[9];
            const float* gp = R_gt + (size_t)b * 9;
            #pragma unroll
            for (int k = 0; k < 9; k++) g[k] = __ldg(gp + k);

            // 4 candidates = 9 conflict-free LDS.128
            float rp[36];
            const float4* p4 = reinterpret_cast<const float4*>(&S[(bl * 64 + m * 4) * 9]);
            #pragma unroll
            for (int k = 0; k < 9; k++) {
                float4 v = p4[k];
                rp[4*k+0] = v.x; rp[4*k+1] = v.y; rp[4*k+2] = v.z; rp[4*k+3] = v.w;
            }

            // M[c][i*3+k] = sum_j rp[c,i,j]*g[k*3+j]; pack candidate pairs
            ull a[9], bq[9];
            #pragma unroll
            for (int e = 0; e < 9; e++) {
                const int i3 = (e / 3) * 3, k3 = (e % 3) * 3;
                float m0 = fmaf(rp[ 0+i3+2], g[k3+2], fmaf(rp[ 0+i3+1], g[k3+1], rp[ 0+i3] * g[k3]));
                float m1 = fmaf(rp[ 9+i3+2], g[k3+2], fmaf(rp[ 9+i3+1], g[k3+1], rp[ 9+i3] * g[k3]));
                float m2 = fmaf(rp[18+i3+2], g[k3+2], fmaf(rp[18+i3+1], g[k3+1], rp[18+i3] * g[k3]));
                float m3 = fmaf(rp[27+i3+2], g[k3+2], fmaf(rp[27+i3+1], g[k3+1], rp[27+i3] * g[k3]));
                asm("mov.b64 %0, {%1, %2};" : "=l"(a[e])  : "f"(m0), "f"(m1));
                asm("mov.b64 %0, {%1, %2};" : "=l"(bq[e]) : "f"(m2), "f"(m3));
            }

            // s-loop: tr[c,s] = <rot[s], M[c]> via duplicated-pair f32x2 (uniform base)
            #pragma unroll
            for (int s = 0; s < 12; s++) {
                const ull* gq = reinterpret_cast<const ull*>(gdup + s * 20);
                ull acc0 = 0ull, acc1 = 0ull;
                #pragma unroll
                for (int h = 0; h < 4; h++) {          // broadcast LDS.128
                    ulonglong2 q = reinterpret_cast<const ulonglong2*>(gq)[h];
                    asm("fma.rn.f32x2 %0, %1, %2, %3;" : "=l"(acc0) : "l"(a[2*h]),    "l"(q.x), "l"(acc0));
                    asm("fma.rn.f32x2 %0, %1, %2, %3;" : "=l"(acc1) : "l"(bq[2*h]),   "l"(q.x), "l"(acc1));
                    asm("fma.rn.f32x2 %0, %1, %2, %3;" : "=l"(acc0) : "l"(a[2*h+1]),  "l"(q.y), "l"(acc0));
                    asm("fma.rn.f32x2 %0, %1, %2, %3;" : "=l"(acc1) : "l"(bq[2*h+1]), "l"(q.y), "l"(acc1));
                }
                ull g8 = gq[8];
                asm("fma.rn.f32x2 %0, %1, %2, %3;" : "=l"(acc0) : "l"(a[8]),  "l"(g8), "l"(acc0));
                asm("fma.rn.f32x2 %0, %1, %2, %3;" : "=l"(acc1) : "l"(bq[8]), "l"(g8), "l"(acc1));

                float2 f0 = *reinterpret_cast<float2*>(&acc0);
                float2 f1 = *reinterpret_cast<float2*>(&acc1);
                cmax = fmaxf(cmax, fmaxf(fmaxf(f0.x, f0.y), fmaxf(f1.x, f1.y)));
            }
        }

        // max over the 16 lanes sharing this b
        #pragma unroll
        for (int w = 8; w >= 1; w >>= 1)
            cmax = fmaxf(cmax, __shfl_xor_sync(0xFFFFFFFFu, cmax, w));

        if (m == 0 && bl < nb) {
            float cosv = (cmax - 1.0f) * 0.5f;
            cosv = fminf(fmaxf(cosv, -1.0f + EPS), 1.0f - EPS);
            atomicAdd(&ssum, acosf(cosv));
        }
        __syncthreads();   // protect buffer p before it is restaged next round
    }

    // ---- publish per-CTA sum; last CTA reduces (counter wraps to 0) ----
    if (tid == 0) {
        g_partial[blockIdx.x] = ssum;
        __threadfence();
        unsigned int old = atomicInc(&g_count, (unsigned int)(grid - 1));
        slast = (old == (unsigned int)(grid - 1));
    }
    __syncthreads();

    if (slast) {
        __shared__ float warpsum[TPB / 32];
        float v = 0.0f;
        for (int i = tid; i < grid; i += TPB) v += __ldcg(&g_partial[i]);
        #pragma unroll
        for (int w = 16; w >= 1; w >>= 1)
            v += __shfl_xor_sync(0xFFFFFFFFu, v, w);
        if ((tid & 31) == 0) warpsum[tid >> 5] = v;
        __syncthreads();
        if (tid < TPB / 32) {
            float w2 = warpsum[tid];
            #pragma unroll
            for (int w = TPB / 64; w >= 1; w >>= 1)
                w2 += __shfl_xor_sync(0xFFu, w2, w);
            if (tid == 0) out[0] = w2 * invB;
        }
    }
}

extern "C" void kernel_launch(void* const* d_in, const int* in_sizes, int n_in,
                              void* d_out, int out_size)
{
    const float* R_pred = (const float*)d_in[0];
    const float* R_gt   = (const float*)d_in[1];
    const float* rot    = (const float*)d_in[2];
    float* out = (float*)d_out;

    const int B = in_sizes[1] / 9;
    const int ntiles = (B + NB - 1) / NB;
    int grid = 6 * 148;                       // 6 CTAs/SM persistent
    if (grid > ntiles) grid = ntiles;

    cudaFuncSetAttribute(geo_pipe, cudaFuncAttributeMaxDynamicSharedMemorySize, SMEM_BYTES);
    geo_pipe<<<grid, TPB, SMEM_BYTES>>>(R_pred, R_gt, rot, out,
                                        B, ntiles, grid, 1.0f / (float)B);
}

// round 13
// speedup vs baseline: 1.3303x; 1.0583x over previous
#include <cuda_runtime.h>
#include <cuda_bf16.h>
#include <cstdint>

#define NB   8            // b's per tile
#define TPB  128          // 16 threads per b, 4 candidates per thread
#define EPS  1e-6f
typedef unsigned long long ull;

#define RP_F     (NB * 576)            // 4608 floats per stage (18432 B)
#define SMEM_BYTES (2 * RP_F * 4)      // 36864 B dynamic (two buffers)

__device__ float g_partial[1024];
__device__ unsigned int g_count = 0;    // self-resets via atomicInc wrap

__global__ __launch_bounds__(TPB, 6)
void geo_tma(const float* __restrict__ R_pred,
             const float* __restrict__ R_gt,
             const float* __restrict__ rot,
             float* __restrict__ out,
             int B, int ntiles, int grid, float invB)
{
    extern __shared__ float sm[];           // 2 x RP_F staging buffers (16B aligned)
    __shared__ alignas(8) ull mbar[2];
    __shared__ float gdup[240];             // rot duplicated pairs, warp-uniform
    __shared__ float ssum;
    __shared__ int slast;

    const int tid = threadIdx.x;
    const int bl  = tid >> 4;               // local b within tile
    const int m   = tid & 15;               // candidate group (4 candidates)

    const uint32_t mb0 = (uint32_t)__cvta_generic_to_shared(&mbar[0]);
    const uint32_t mb1 = (uint32_t)__cvta_generic_to_shared(&mbar[1]);
    const uint32_t sm0 = (uint32_t)__cvta_generic_to_shared(sm);

    if (tid < 108) {
        const int s = tid / 9, e = tid - s * 9;
        float v = __ldg(rot + tid);
        gdup[s * 20 + e * 2]     = v;
        gdup[s * 20 + e * 2 + 1] = v;
    }
    if (tid == 0) {
        ssum = 0.0f;
        asm volatile("mbarrier.init.shared.b64 [%0], 1;" :: "r"(mb0));
        asm volatile("mbarrier.init.shared.b64 [%0], 1;" :: "r"(mb1));
    }
    __syncthreads();

    // one TMA bulk copy stages a whole tile (tid==0 only)
    auto stage = [&](int t, int p) {
        const int nb = min(NB, B - t * NB);
        const uint32_t bytes = (uint32_t)nb * 2304u;
        const uint32_t mb = p ? mb1 : mb0;
        asm volatile("mbarrier.arrive.expect_tx.shared.b64 _, [%0], %1;"
                     :: "r"(mb), "r"(bytes));
        asm volatile("cp.async.bulk.shared::cta.global.mbarrier::complete_tx::bytes "
                     "[%0], [%1], %2, [%3];"
                     :: "r"(sm0 + (uint32_t)p * (RP_F * 4u)),
                        "l"(R_pred + (size_t)t * NB * 576), "r"(bytes), "r"(mb)
                     : "memory");
    };

    if (tid == 0) {
        stage(blockIdx.x, 0);
        if (blockIdx.x + grid < ntiles) stage(blockIdx.x + grid, 1);
    }

    int ph0 = 0, ph1 = 0;
    int p = 0;
    for (int t = blockIdx.x; t < ntiles; t += grid, p ^= 1) {
        // wait for buffer p (parity)
        {
            const uint32_t mb = p ? mb1 : mb0;
            const uint32_t phase = (uint32_t)(p ? ph1 : ph0);
            uint32_t done;
            do {
                asm volatile(
                    "{\n\t.reg .pred P;\n\t"
                    "mbarrier.try_wait.parity.acquire.cta.shared::cta.b64 P, [%1], %2, 0x989680;\n\t"
                    "selp.b32 %0, 1, 0, P;\n\t}"
                    : "=r"(done) : "r"(mb), "r"(phase) : "memory");
            } while (!done);
            if (p) ph1 ^= 1; else ph0 ^= 1;
        }

        const int nb = min(NB, B - t * NB);
        const float* S = sm + p * RP_F;
        float cmax = -1e30f;

        if (bl < nb) {
            const int b = t * NB + bl;

            // R_gt[b]: 9 x LDG.32, L2-resident
            float g[9];
            const float* gp = R_gt + (size_t)b * 9;
            #pragma unroll
            for (int k = 0; k < 9; k++) g[k] = __ldg(gp + k);

            // 4 candidates = 9 conflict-free LDS.128
            float rp[36];
            const float4* p4 = reinterpret_cast<const float4*>(&S[(bl * 64 + m * 4) * 9]);
            #pragma unroll
            for (int k = 0; k < 9; k++) {
                float4 v = p4[k];
                rp[4*k+0] = v.x; rp[4*k+1] = v.y; rp[4*k+2] = v.z; rp[4*k+3] = v.w;
            }

            // M[c][i*3+k] = sum_j rp[c,i,j]*g[k*3+j]; pack candidate pairs
            ull a[9], bq[9];
            #pragma unroll
            for (int e = 0; e < 9; e++) {
                const int i3 = (e / 3) * 3, k3 = (e % 3) * 3;
                float m0 = fmaf(rp[ 0+i3+2], g[k3+2], fmaf(rp[ 0+i3+1], g[k3+1], rp[ 0+i3] * g[k3]));
                float m1 = fmaf(rp[ 9+i3+2], g[k3+2], fmaf(rp[ 9+i3+1], g[k3+1], rp[ 9+i3] * g[k3]));
                float m2 = fmaf(rp[18+i3+2], g[k3+2], fmaf(rp[18+i3+1], g[k3+1], rp[18+i3] * g[k3]));
                float m3 = fmaf(rp[27+i3+2], g[k3+2], fmaf(rp[27+i3+1], g[k3+1], rp[27+i3] * g[k3]));
                asm("mov.b64 %0, {%1, %2};" : "=l"(a[e])  : "f"(m0), "f"(m1));
                asm("mov.b64 %0, {%1, %2};" : "=l"(bq[e]) : "f"(m2), "f"(m3));
            }

            // s-loop: tr[c,s] = <rot[s], M[c]> via duplicated-pair f32x2
            #pragma unroll
            for (int s = 0; s < 12; s++) {
                const ull* gq = reinterpret_cast<const ull*>(gdup + s * 20);
                ull acc0 = 0ull, acc1 = 0ull;
                #pragma unroll
                for (int h = 0; h < 4; h++) {          // broadcast LDS.128
                    ulonglong2 q = reinterpret_cast<const ulonglong2*>(gq)[h];
                    asm("fma.rn.f32x2 %0, %1, %2, %3;" : "=l"(acc0) : "l"(a[2*h]),    "l"(q.x), "l"(acc0));
                    asm("fma.rn.f32x2 %0, %1, %2, %3;" : "=l"(acc1) : "l"(bq[2*h]),   "l"(q.x), "l"(acc1));
                    asm("fma.rn.f32x2 %0, %1, %2, %3;" : "=l"(acc0) : "l"(a[2*h+1]),  "l"(q.y), "l"(acc0));
                    asm("fma.rn.f32x2 %0, %1, %2, %3;" : "=l"(acc1) : "l"(bq[2*h+1]), "l"(q.y), "l"(acc1));
                }
                ull g8 = gq[8];
                asm("fma.rn.f32x2 %0, %1, %2, %3;" : "=l"(acc0) : "l"(a[8]),  "l"(g8), "l"(acc0));
                asm("fma.rn.f32x2 %0, %1, %2, %3;" : "=l"(acc1) : "l"(bq[8]), "l"(g8), "l"(acc1));

                float2 f0 = *reinterpret_cast<float2*>(&acc0);
                float2 f1 = *reinterpret_cast<float2*>(&acc1);
                cmax = fmaxf(cmax, fmaxf(fmaxf(f0.x, f0.y), fmaxf(f1.x, f1.y)));
            }
        }

        // max over the 16 lanes sharing this b
        #pragma unroll
        for (int w = 8; w >= 1; w >>= 1)
            cmax = fmaxf(cmax, __shfl_xor_sync(0xFFFFFFFFu, cmax, w));

        if (m == 0 && bl < nb) {
            float cosv = (cmax - 1.0f) * 0.5f;
            cosv = fminf(fmaxf(cosv, -1.0f + EPS), 1.0f - EPS);
            atomicAdd(&ssum, acosf(cosv));
        }
        __syncthreads();           // all threads done reading buffer p

        // restage buffer p with tile t + 2*grid
        const int t2 = t + 2 * grid;
        if (tid == 0 && t2 < ntiles) stage(t2, p);
    }

    // ---- publish per-CTA sum; last CTA reduces (counter wraps to 0) ----
    if (tid == 0) {
        g_partial[blockIdx.x] = ssum;
        __threadfence();
        unsigned int old = atomicInc(&g_count, (unsigned int)(grid - 1));
        slast = (old == (unsigned int)(grid - 1));
    }
    __syncthreads();

    if (slast) {
        __shared__ float warpsum[TPB / 32];
        float v = 0.0f;
        for (int i = tid; i < grid; i += TPB) v += __ldcg(&g_partial[i]);
        #pragma unroll
        for (int w = 16; w >= 1; w >>= 1)
            v += __shfl_xor_sync(0xFFFFFFFFu, v, w);
        if ((tid & 31) == 0) warpsum[tid >> 5] = v;
        __syncthreads();
        if (tid < TPB / 32) {
            float w2 = warpsum[tid];
            #pragma unroll
            for (int w = TPB / 64; w >= 1; w >>= 1)
                w2 += __shfl_xor_sync(0xFFu, w2, w);
            if (tid == 0) out[0] = w2 * invB;
        }
    }
}

extern "C" void kernel_launch(void* const* d_in, const int* in_sizes, int n_in,
                              void* d_out, int out_size)
{
    const float* R_pred = (const float*)d_in[0];
    const float* R_gt   = (const float*)d_in[1];
    const float* rot    = (const float*)d_in[2];
    float* out = (float*)d_out;

    const int B = in_sizes[1] / 9;
    const int ntiles = (B + NB - 1) / NB;
    int grid = 6 * 148;                       // 6 CTAs/SM persistent
    if (grid > ntiles) grid = ntiles;

    cudaFuncSetAttribute(geo_tma, cudaFuncAttributeMaxDynamicSharedMemorySize, SMEM_BYTES);
    geo_tma<<<grid, TPB, SMEM_BYTES>>>(R_pred, R_gt, rot, out,
                                       B, ntiles, grid, 1.0f / (float)B);
}